// round 15
// baseline (speedup 1.0000x reference)
#include <cuda_runtime.h>
#include <cuda_fp16.h>
#include <math.h>

#define PB  128
#define PH  100
#define PC  32
#define PK  4
#define PD  400
#define PDP 448
#define PE  200
#define PCW 100
#define PN  (PB*PC)

#define KC   64
#define NCH  7
#define AS   72                      // smem row stride (halves) = 144B
#define A_PLANE (128*AS)             // 9216 halves
#define B_PLANE (208*AS)             // 14976 halves
#define BUF_HALVES (A_PLANE + 2*B_PLANE)       // 39168 halves
#define SMEMA_BYTES (2*BUF_HALVES*2)           // 156672 B

typedef unsigned long long ull;
typedef unsigned int uint;

__device__ __align__(16) float u_g[PB*PK*PD];
__device__ __align__(16) float uW_g[PB*PK*PE];
__device__ __align__(16) float s_g[PB*PK*PH];
__device__ __align__(16) float zC_g[(size_t)PN*PK*PE];

__device__ __align__(16) __half hisH[PB*PK*PH*PDP];
__device__ __align__(16) __half WTh[PK*PE*PDP];
__device__ __align__(16) __half WTl[PK*PE*PDP];

// ---- helpers ----
__device__ __forceinline__ ull pack2(float a, float b) {
    ull r; asm("mov.b64 %0, {%1, %2};" : "=l"(r) : "f"(a), "f"(b)); return r;
}
__device__ __forceinline__ void unpack2(ull v, float& a, float& b) {
    asm("mov.b64 {%0, %1}, %2;" : "=f"(a), "=f"(b) : "l"(v));
}
__device__ __forceinline__ void fma2(ull& d, ull a, ull b) {
    asm("fma.rn.f32x2 %0, %1, %2, %0;" : "+l"(d) : "l"(a), "l"(b));
}
__device__ __forceinline__ float tanh_fast(float x) {
    return __fdividef(2.f, 1.f + __expf(-2.f * x)) - 1.f;
}
__device__ __forceinline__ void mma16816(
    float& c0, float& c1, float& c2, float& c3,
    uint a0, uint a1, uint a2, uint a3, uint b0, uint b1)
{
    asm volatile(
        "mma.sync.aligned.m16n8k16.row.col.f32.f16.f16.f32 "
        "{%0,%1,%2,%3}, {%4,%5,%6,%7}, {%8,%9}, {%0,%1,%2,%3};"
        : "+f"(c0), "+f"(c1), "+f"(c2), "+f"(c3)
        : "r"(a0), "r"(a1), "r"(a2), "r"(a3), "r"(b0), "r"(b1));
}
__device__ __forceinline__ void ldsm_x4(uint& r0, uint& r1, uint& r2, uint& r3, uint addr) {
    asm volatile("ldmatrix.sync.aligned.m8n8.x4.shared.b16 {%0,%1,%2,%3}, [%4];"
                 : "=r"(r0), "=r"(r1), "=r"(r2), "=r"(r3) : "r"(addr));
}
__device__ __forceinline__ void ldsm_x2(uint& r0, uint& r1, uint addr) {
    asm volatile("ldmatrix.sync.aligned.m8n8.x2.shared.b16 {%0,%1}, [%2];"
                 : "=r"(r0), "=r"(r1) : "r"(addr));
}
__device__ __forceinline__ ull pack4h(float x0, float x1, float x2, float x3) {
    __half2 h01 = __halves2half2(__float2half_rn(x0), __float2half_rn(x1));
    __half2 h23 = __halves2half2(__float2half_rn(x2), __float2half_rn(x3));
    uint u0 = *(uint*)&h01, u1 = *(uint*)&h23;
    return (ull)u0 | ((ull)u1 << 32);
}
__device__ __forceinline__ unsigned smem_u32(const void* p) {
    return (unsigned)__cvta_generic_to_shared(p);
}
__device__ __forceinline__ void cp16(__half* dst, const __half* src) {
    asm volatile("cp.async.cg.shared.global [%0], [%1], 16;"
                 :: "r"(smem_u32(dst)), "l"(src));
}
__device__ __forceinline__ void cp_commit() {
    asm volatile("cp.async.commit_group;");
}
template <int N>
__device__ __forceinline__ void cp_wait() {
    asm volatile("cp.async.wait_group %0;" :: "n"(N));
}

// ---- P: his -> hisH, W_att -> WTh/WTl; zero s_g. 2 units/thread (MLP=2) ----
#define PRE_UNITS (PB*PK*PH*112)
__global__ void __launch_bounds__(256) preconv(
    const float* __restrict__ his, const float* __restrict__ W_att)
{
    const int u0 = blockIdx.x*256 + threadIdx.x;
    if (u0 < PB*PK*PH) s_g[u0] = 0.f;

    if (u0 < PK*PE*112) {
        const int ke = u0 / 112, d4 = u0 - ke*112;
        const int k = ke / PE, e = ke - k*PE;
        const size_t dst = (size_t)ke*PDP + d4*4;
        if (d4 < 100) {
            float w0 = W_att[((size_t)k*PD + d4*4    )*PE + e];
            float w1 = W_att[((size_t)k*PD + d4*4 + 1)*PE + e];
            float w2 = W_att[((size_t)k*PD + d4*4 + 2)*PE + e];
            float w3 = W_att[((size_t)k*PD + d4*4 + 3)*PE + e];
            float h0 = __half2float(__float2half_rn(w0));
            float h1 = __half2float(__float2half_rn(w1));
            float h2 = __half2float(__float2half_rn(w2));
            float h3 = __half2float(__float2half_rn(w3));
            *(ull*)(WTh + dst) = pack4h(w0, w1, w2, w3);
            *(ull*)(WTl + dst) = pack4h(w0-h0, w1-h1, w2-h2, w3-h3);
        } else {
            *(ull*)(WTh + dst) = 0ull;
            *(ull*)(WTl + dst) = 0ull;
        }
    }

    #pragma unroll
    for (int half = 0; half < 2; ++half) {
        const int u = u0 + half*(PRE_UNITS/2);
        if (u >= PRE_UNITS) break;
        const int bkh = u / 112, c4 = u - bkh*112;
        const int bk = bkh / PH, h = bkh - bk*PH;
        const int b = bk >> 2, k = bk & 3;
        const size_t dst = (size_t)(bk*PH + h)*PDP + c4*4;
        if (c4 < 100) {
            float4 v = *(const float4*)(his + ((size_t)b*PH + h)*(PK*PD) + k*PD + c4*4);
            *(ull*)(hisH + dst) = pack4h(v.x, v.y, v.z, v.w);
        } else {
            *(ull*)(hisH + dst) = 0ull;
        }
    }
}

// -----------------------------------------------------------------------------
// Kernel A1: m32-per-warp flat GEMM, KC=64, double-buffered cp.async,
// fragment loads via LDSM (x4/x2) instead of scalar LDS.
// -----------------------------------------------------------------------------
__global__ void __launch_bounds__(256, 1) kernelA1(
    const float* __restrict__ b_att, const float* __restrict__ q_att)
{
    extern __shared__ __half smh[];

    const int tid  = threadIdx.x;
    const int warp = tid >> 5;
    const int lane = tid & 31;
    const int g    = lane >> 2;
    const int qq   = lane & 3;
    const int i8   = lane & 7;
    const int grp4 = lane >> 3;
    const int mrow0 = (warp >> 1) * 32;
    const int nbase = (warp & 1) * 104;

    const int mtile = blockIdx.x;
    const int k     = blockIdx.y;
    const int r0g   = mtile * 128;

    const __half* srcBH = WTh + (size_t)k*PE*PDP;
    const __half* srcBL = WTl + (size_t)k*PE*PDP;

    auto load_tile = [&](int buf, int k0) {
        __half* aHi = smh + buf*BUF_HALVES;
        __half* bHi = aHi + A_PLANE;
        __half* bLo = bHi + B_PLANE;
        #pragma unroll
        for (int it = 0; it < 4; ++it) {
            int ua = tid + it*256;
            int row = ua >> 3, cc = ua & 7;
            int r = r0g + row;
            int b = r / 100, h = r - b*100;
            const __half* s = hisH + ((size_t)(b*4 + k)*PH + h)*PDP + k0 + cc*8;
            cp16(aHi + row*AS + cc*8, s);
        }
        #pragma unroll
        for (int it = 0; it < 13; ++it) {
            int ub = tid + it*256;
            if (ub < 3200) {
                int row = ub >> 4, rem = ub & 15;
                int pl = rem >> 3, cc = rem & 7;
                const __half* s = (pl ? srcBL : srcBH) + (size_t)row*PDP + k0 + cc*8;
                cp16((pl ? bLo : bHi) + row*AS + cc*8, s);
            }
        }
    };

    // per-lane LDSM byte offsets (within a plane)
    const uint aoff  = (uint)(((mrow0 + (grp4 & 1)*8 + i8)*AS + (grp4 >> 1)*8) * 2);
    const uint boff  = (uint)(((nbase + (grp4 >> 1)*8 + i8)*AS + (grp4 & 1)*8) * 2);
    const uint boff2 = (uint)(((nbase + i8)*AS + ((lane >> 3) & 1)*8) * 2);  // x2-safe

    float c[13][8];
    #pragma unroll
    for (int t = 0; t < 13; ++t)
        #pragma unroll
        for (int j = 0; j < 8; ++j) c[t][j] = 0.f;

    load_tile(0, 0);
    cp_commit();

    for (int ch = 0; ch < NCH; ++ch) {
        const int buf = ch & 1;
        if (ch < NCH - 1) {
            load_tile(buf ^ 1, (ch+1)*KC);
            cp_commit();
            cp_wait<1>();
        } else {
            cp_wait<0>();
        }
        __syncthreads();

        const uint aHiB = smem_u32(smh + buf*BUF_HALVES);
        const uint bHiB = aHiB + A_PLANE*2;
        const uint bLoB = bHiB + B_PLANE*2;

        #pragma unroll
        for (int ks = 0; ks < 4; ++ks) {
            const uint kk2 = (uint)(ks * 16 * 2);
            uint a0[4], a1[4];
            ldsm_x4(a0[0], a0[1], a0[2], a0[3], aHiB + aoff + kk2);
            ldsm_x4(a1[0], a1[1], a1[2], a1[3], aHiB + aoff + 16*AS*2 + kk2);
            #pragma unroll
            for (int t2 = 0; t2 < 6; ++t2) {
                const uint toff = (uint)(t2 * 16 * AS * 2);
                uint bh[4], bl[4];
                ldsm_x4(bh[0], bh[1], bh[2], bh[3], bHiB + boff + toff + kk2);
                ldsm_x4(bl[0], bl[1], bl[2], bl[3], bLoB + boff + toff + kk2);
                const int t = 2*t2;
                mma16816(c[t][0], c[t][1], c[t][2], c[t][3],
                         a0[0], a0[1], a0[2], a0[3], bh[0], bh[1]);
                mma16816(c[t][0], c[t][1], c[t][2], c[t][3],
                         a0[0], a0[1], a0[2], a0[3], bl[0], bl[1]);
                mma16816(c[t][4], c[t][5], c[t][6], c[t][7],
                         a1[0], a1[1], a1[2], a1[3], bh[0], bh[1]);
                mma16816(c[t][4], c[t][5], c[t][6], c[t][7],
                         a1[0], a1[1], a1[2], a1[3], bl[0], bl[1]);
                mma16816(c[t+1][0], c[t+1][1], c[t+1][2], c[t+1][3],
                         a0[0], a0[1], a0[2], a0[3], bh[2], bh[3]);
                mma16816(c[t+1][0], c[t+1][1], c[t+1][2], c[t+1][3],
                         a0[0], a0[1], a0[2], a0[3], bl[2], bl[3]);
                mma16816(c[t+1][4], c[t+1][5], c[t+1][6], c[t+1][7],
                         a1[0], a1[1], a1[2], a1[3], bh[2], bh[3]);
                mma16816(c[t+1][4], c[t+1][5], c[t+1][6], c[t+1][7],
                         a1[0], a1[1], a1[2], a1[3], bl[2], bl[3]);
            }
            {   // tile 12 (x2, lane-safe offsets)
                const uint toff = (uint)(6 * 16 * AS * 2);
                uint bh0, bh1, bl0, bl1;
                ldsm_x2(bh0, bh1, bHiB + boff2 + toff + kk2);
                ldsm_x2(bl0, bl1, bLoB + boff2 + toff + kk2);
                mma16816(c[12][0], c[12][1], c[12][2], c[12][3],
                         a0[0], a0[1], a0[2], a0[3], bh0, bh1);
                mma16816(c[12][0], c[12][1], c[12][2], c[12][3],
                         a0[0], a0[1], a0[2], a0[3], bl0, bl1);
                mma16816(c[12][4], c[12][5], c[12][6], c[12][7],
                         a1[0], a1[1], a1[2], a1[3], bh0, bh1);
                mma16816(c[12][4], c[12][5], c[12][6], c[12][7],
                         a1[0], a1[1], a1[2], a1[3], bl0, bl1);
            }
        }
        __syncthreads();
    }

    float pr[4] = {0.f, 0.f, 0.f, 0.f};
    #pragma unroll
    for (int t = 0; t < 13; ++t) {
        const int e0 = nbase + t*8 + qq*2;
        if (e0 < PE) {
            const float q0 = q_att[k*PE + e0],   bb0 = b_att[k*PE + e0];
            const float q1 = q_att[k*PE + e0+1], bb1 = b_att[k*PE + e0+1];
            pr[0] += q0 * tanh_fast(c[t][0] + bb0) + q1 * tanh_fast(c[t][1] + bb1);
            pr[1] += q0 * tanh_fast(c[t][2] + bb0) + q1 * tanh_fast(c[t][3] + bb1);
            pr[2] += q0 * tanh_fast(c[t][4] + bb0) + q1 * tanh_fast(c[t][5] + bb1);
            pr[3] += q0 * tanh_fast(c[t][6] + bb0) + q1 * tanh_fast(c[t][7] + bb1);
        }
    }
    #pragma unroll
    for (int i = 0; i < 4; ++i) {
        pr[i] += __shfl_xor_sync(0xffffffffu, pr[i], 1);
        pr[i] += __shfl_xor_sync(0xffffffffu, pr[i], 2);
    }
    if (qq == 0) {
        #pragma unroll
        for (int i = 0; i < 4; ++i) {
            int r = r0g + mrow0 + ((i & 1) ? 8 : 0) + ((i >> 1) ? 16 : 0) + g;
            int b = r / 100, h = r - b*100;
            atomicAdd(&s_g[(b*4 + k)*PH + h], pr[i]);
        }
    }
}

// ---- Kernel A2: R14 version (512 thr, split phases, writes out_u) ----
__global__ void __launch_bounds__(512) kernelA2(
    const float* __restrict__ W_lin, const float* __restrict__ b_lin,
    float* __restrict__ out_u)
{
    __shared__ float s_s[PH];
    __shared__ float u_s[PD];
    __shared__ float up2[PD];
    __shared__ float uwp[2][PE];
    __shared__ float red_s[2];

    const int bk = blockIdx.x;
    const int b = bk >> 2, k = bk & 3;
    const int tid = threadIdx.x;
    const int grp = tid >> 8;
    const int t   = tid & 255;
    const __half* hisB16 = hisH + (size_t)bk*PH*PDP;

    if (tid < PH) s_s[tid] = s_g[bk*PH + tid];
    __syncthreads();

    if (tid < 32) {
        float m = -1e30f;
        for (int h = tid; h < PH; h += 32) m = fmaxf(m, s_s[h]);
        #pragma unroll
        for (int off = 16; off; off >>= 1)
            m = fmaxf(m, __shfl_xor_sync(0xffffffffu, m, off));
        if (tid == 0) { red_s[0] = m; red_s[1] = 0.f; }
    }
    __syncthreads();
    const float mx = red_s[0];
    if (tid < PH) {
        float ex = __expf(s_s[tid] - mx);
        s_s[tid] = ex;
        atomicAdd(&red_s[1], ex);
    }
    __syncthreads();
    const float inv = 1.f / red_s[1];

    if (t < 200) {
        const int d2 = t;
        const int h0 = grp ? 52 : 0;
        const int h1 = grp ? 100 : 52;
        float a0 = 0.f, b0 = 0.f, a1 = 0.f, b1 = 0.f;
        float a2 = 0.f, b2 = 0.f, a3 = 0.f, b3 = 0.f;
        #pragma unroll 4
        for (int h = h0; h < h1; h += 4) {
            float2 v0 = __half22float2(*(const __half2*)(hisB16 + (size_t)h*PDP + 2*d2));
            float2 v1 = __half22float2(*(const __half2*)(hisB16 + (size_t)(h+1)*PDP + 2*d2));
            float2 v2 = __half22float2(*(const __half2*)(hisB16 + (size_t)(h+2)*PDP + 2*d2));
            float2 v3 = __half22float2(*(const __half2*)(hisB16 + (size_t)(h+3)*PDP + 2*d2));
            a0 += s_s[h]   * v0.x;  b0 += s_s[h]   * v0.y;
            a1 += s_s[h+1] * v1.x;  b1 += s_s[h+1] * v1.y;
            a2 += s_s[h+2] * v2.x;  b2 += s_s[h+2] * v2.y;
            a3 += s_s[h+3] * v3.x;  b3 += s_s[h+3] * v3.y;
        }
        float* dst = grp ? up2 : u_s;
        dst[2*d2]   = (a0 + a1) + (a2 + a3);
        dst[2*d2+1] = (b0 + b1) + (b2 + b3);
    }
    __syncthreads();

    if (tid < PD) {
        float uu = (u_s[tid] + up2[tid]) * inv;
        u_s[tid] = uu;
        u_g[bk*PD + tid] = uu;
    }
    __syncthreads();

    if (t < PE) {
        const int e = t;
        const int d0 = grp * 200;
        float a0 = 0.f, a1 = 0.f, a2 = 0.f, a3 = 0.f;
        float a4 = 0.f, a5 = 0.f, a6 = 0.f, a7 = 0.f;
        #pragma unroll 2
        for (int d = d0; d < d0 + 200; d += 8) {
            a0 += u_s[d]   * W_lin[(size_t)(d)*PE + e];
            a1 += u_s[d+1] * W_lin[(size_t)(d+1)*PE + e];
            a2 += u_s[d+2] * W_lin[(size_t)(d+2)*PE + e];
            a3 += u_s[d+3] * W_lin[(size_t)(d+3)*PE + e];
            a4 += u_s[d+4] * W_lin[(size_t)(d+4)*PE + e];
            a5 += u_s[d+5] * W_lin[(size_t)(d+5)*PE + e];
            a6 += u_s[d+6] * W_lin[(size_t)(d+6)*PE + e];
            a7 += u_s[d+7] * W_lin[(size_t)(d+7)*PE + e];
        }
        uwp[grp][e] = ((a0 + a1) + (a2 + a3)) + ((a4 + a5) + (a6 + a7));
    }
    __syncthreads();

    if (tid < PE)
        uW_g[bk*PE + tid] = b_lin[tid] + uwp[0][tid] + uwp[1][tid];

    for (int idx = tid; idx < 32*(PD/4); idx += 512) {
        int cc = idx / (PD/4), i4 = idx - cc*(PD/4);
        float4 v = *(const float4*)(u_s + i4*4);
        *(float4*)(out_u + ((size_t)(b*PC + cc)*PK + k)*PD + i4*4) = v;
    }
}

// ---- Kernel C1: unchanged ----
__global__ void __launch_bounds__(256) kernelC1(
    const float* __restrict__ cwt, const float* __restrict__ W_lin)
{
    extern __shared__ float sm[];
    float* W2 = sm;
    float* cw = W2 + PCW*PE;

    const int tid = threadIdx.x;
    const int tx = tid & 7;
    const int ty = tid >> 3;
    const int row0 = blockIdx.x * 64;

    for (int i = tid; i < PCW*PE; i += 256) W2[i] = W_lin[PD*PE + i];
    for (int i = tid; i < 64*PCW; i += 256) cw[i] = cwt[(size_t)row0*PCW + i];
    __syncthreads();

    ull acc2[2][12];
    float accS[2] = {0.f, 0.f};
    #pragma unroll
    for (int r = 0; r < 2; ++r)
        #pragma unroll
        for (int j = 0; j < 12; ++j) acc2[r][j] = 0ull;

    const float* c0p = cw + (ty*2)*PCW;
    const float* c1p = c0p + PCW;

    #pragma unroll 2
    for (int f = 0; f < PCW; ++f) {
        const float c0 = c0p[f], c1 = c1p[f];
        const ull cc0 = pack2(c0, c0), cc1 = pack2(c1, c1);
        const float* wrow = W2 + f*PE + tx*2;
        #pragma unroll
        for (int j = 0; j < 12; ++j) {
            ull w2v = *(const ull*)(wrow + j*16);
            fma2(acc2[0][j], cc0, w2v);
            fma2(acc2[1][j], cc1, w2v);
        }
        const float wl = W2[f*PE + 192 + tx];
        accS[0] += c0 * wl;
        accS[1] += c1 * wl;
    }

    #pragma unroll
    for (int rr = 0; rr < 2; ++rr) {
        const int gidx = row0 + ty*2 + rr;
        float* zrow = zC_g + (size_t)gidx*PE;
        #pragma unroll
        for (int j = 0; j < 12; ++j) {
            float z0, z1; unpack2(acc2[rr][j], z0, z1);
            zrow[tx*2 + j*16]     = z0;
            zrow[tx*2 + j*16 + 1] = z1;
        }
        zrow[192 + tx] = accS[rr];
    }
}

// ---- Kernel D: unchanged ----
__global__ void __launch_bounds__(128) kernelD(
    const float* __restrict__ cdd, const float* __restrict__ q_vec,
    float* __restrict__ out_scores)
{
    const int n = blockIdx.x;
    const int b = n >> 5;
    const int tid = threadIdx.x;
    const int k = tid >> 5;
    const int lane = tid & 31;
    __shared__ float dot_s[4];
    __shared__ float sk_s[4];

    {
        const float* z = zC_g + ((size_t)n*PK + k)*PE;
        const float* uWp = uW_g + ((b << 2) + k)*PE;
        float p = 0.f;
        #pragma unroll
        for (int e = lane; e < PE; e += 32)
            p += q_vec[e] * tanh_fast(z[e] + uWp[e]);
        #pragma unroll
        for (int off = 16; off; off >>= 1)
            p += __shfl_xor_sync(0xffffffffu, p, off);
        if (lane == 0) sk_s[k] = p;
    }
    {
        const float* up = u_g + (size_t)((b << 2) + k)*PD;
        const float* cp = cdd + ((size_t)n*PK + k)*PD;
        float a = 0.f;
        for (int d = lane; d < PD; d += 32) a += up[d] * cp[d];
        #pragma unroll
        for (int off = 16; off; off >>= 1)
            a += __shfl_xor_sync(0xffffffffu, a, off);
        if (lane == 0) dot_s[k] = a;
    }
    __syncthreads();

    if (tid == 0) {
        const float s0 = sk_s[0], s1 = sk_s[1], s2 = sk_s[2], s3 = sk_s[3];
        const float m = fmaxf(fmaxf(s0, s1), fmaxf(s2, s3));
        const float w0 = __expf(s0 - m), w1 = __expf(s1 - m);
        const float w2 = __expf(s2 - m), w3 = __expf(s3 - m);
        out_scores[n] = (w0*dot_s[0] + w1*dot_s[1] + w2*dot_s[2] + w3*dot_s[3])
                        / (w0 + w1 + w2 + w3);
    }
}

extern "C" void kernel_launch(void* const* d_in, const int* in_sizes, int n_in,
                              void* d_out, int out_size)
{
    const float* his   = (const float*)d_in[0];
    const float* cdd   = (const float*)d_in[1];
    const float* cwt   = (const float*)d_in[2];
    const float* W_att = (const float*)d_in[3];
    const float* b_att = (const float*)d_in[4];
    const float* q_att = (const float*)d_in[5];
    const float* W_lin = (const float*)d_in[6];
    const float* b_lin = (const float*)d_in[7];
    const float* q_vec = (const float*)d_in[8];
    float* out = (float*)d_out;
    (void)in_sizes; (void)n_in; (void)out_size;

    static cudaStream_t s2 = nullptr;
    static cudaEvent_t evFork = nullptr, evJoin = nullptr;
    if (s2 == nullptr) {
        cudaStreamCreateWithFlags(&s2, cudaStreamNonBlocking);
        cudaEventCreateWithFlags(&evFork, cudaEventDisableTiming);
        cudaEventCreateWithFlags(&evJoin, cudaEventDisableTiming);
    }

    const int smemC = (PCW*PE + 64*PCW) * (int)sizeof(float);
    cudaFuncSetAttribute(kernelC1, cudaFuncAttributeMaxDynamicSharedMemorySize, smemC);
    cudaFuncSetAttribute(kernelA1, cudaFuncAttributeMaxDynamicSharedMemorySize, SMEMA_BYTES);

    cudaEventRecord(evFork, 0);
    cudaStreamWaitEvent(s2, evFork, 0);
    kernelC1<<<(PN*PK)/64, 256, smemC, s2>>>(cwt, W_lin);

    preconv<<<(PRE_UNITS/2 + 255)/256, 256>>>(his, W_att);
    kernelA1<<<dim3(100, 4), 256, SMEMA_BYTES>>>(b_att, q_att);
    kernelA2<<<PB*PK, 512>>>(W_lin, b_lin, out + PN);

    cudaEventRecord(evJoin, s2);
    cudaStreamWaitEvent(0, evJoin, 0);
    kernelD<<<PN, 128>>>(cdd, q_vec, out);
}

// round 16
// speedup vs baseline: 1.1961x; 1.1961x over previous
#include <cuda_runtime.h>
#include <cuda_fp16.h>
#include <math.h>

#define PB  128
#define PH  100
#define PC  32
#define PK  4
#define PD  400
#define PDP 448
#define PE  200
#define PCW 100
#define PN  (PB*PC)

#define KC   64
#define NCH  7
#define AS   72                      // smem row stride (halves) = 144B
#define A_PLANE (128*AS)             // 9216 halves
#define B_PLANE (208*AS)             // 14976 halves
#define BUF_HALVES (A_PLANE + B_PLANE)         // 24192 halves (B hi only)
#define SMEMA_BYTES (2*BUF_HALVES*2)           // 96768 B

typedef unsigned long long ull;
typedef unsigned int uint;

__device__ __align__(16) float u_g[PB*PK*PD];
__device__ __align__(16) float uW_g[PB*PK*PE];
__device__ __align__(16) float s_g[PB*PK*PH];
__device__ __align__(16) float zC_g[(size_t)PN*PK*PE];

__device__ __align__(16) __half hisH[PB*PK*PH*PDP];   // pads stay 0 (zero-init)
__device__ __align__(16) __half WTh[PK*PE*PDP];       // pads stay 0 (zero-init)

// ---- helpers ----
__device__ __forceinline__ ull pack2(float a, float b) {
    ull r; asm("mov.b64 %0, {%1, %2};" : "=l"(r) : "f"(a), "f"(b)); return r;
}
__device__ __forceinline__ void unpack2(ull v, float& a, float& b) {
    asm("mov.b64 {%0, %1}, %2;" : "=f"(a), "=f"(b) : "l"(v));
}
__device__ __forceinline__ void fma2(ull& d, ull a, ull b) {
    asm("fma.rn.f32x2 %0, %1, %2, %0;" : "+l"(d) : "l"(a), "l"(b));
}
__device__ __forceinline__ float tanh_fast(float x) {
    return __fdividef(2.f, 1.f + __expf(-2.f * x)) - 1.f;
}
__device__ __forceinline__ void mma16816(
    float& c0, float& c1, float& c2, float& c3,
    uint a0, uint a1, uint a2, uint a3, uint b0, uint b1)
{
    asm volatile(
        "mma.sync.aligned.m16n8k16.row.col.f32.f16.f16.f32 "
        "{%0,%1,%2,%3}, {%4,%5,%6,%7}, {%8,%9}, {%0,%1,%2,%3};"
        : "+f"(c0), "+f"(c1), "+f"(c2), "+f"(c3)
        : "r"(a0), "r"(a1), "r"(a2), "r"(a3), "r"(b0), "r"(b1));
}
__device__ __forceinline__ void ldsm_x4(uint& r0, uint& r1, uint& r2, uint& r3, uint addr) {
    asm volatile("ldmatrix.sync.aligned.m8n8.x4.shared.b16 {%0,%1,%2,%3}, [%4];"
                 : "=r"(r0), "=r"(r1), "=r"(r2), "=r"(r3) : "r"(addr));
}
__device__ __forceinline__ void ldsm_x2(uint& r0, uint& r1, uint addr) {
    asm volatile("ldmatrix.sync.aligned.m8n8.x2.shared.b16 {%0,%1}, [%2];"
                 : "=r"(r0), "=r"(r1) : "r"(addr));
}
__device__ __forceinline__ ull pack4h(float x0, float x1, float x2, float x3) {
    __half2 h01 = __halves2half2(__float2half_rn(x0), __float2half_rn(x1));
    __half2 h23 = __halves2half2(__float2half_rn(x2), __float2half_rn(x3));
    uint u0 = *(uint*)&h01, u1 = *(uint*)&h23;
    return (ull)u0 | ((ull)u1 << 32);
}
__device__ __forceinline__ unsigned smem_u32(const void* p) {
    return (unsigned)__cvta_generic_to_shared(p);
}
__device__ __forceinline__ void cp16(__half* dst, const __half* src) {
    asm volatile("cp.async.cg.shared.global [%0], [%1], 16;"
                 :: "r"(smem_u32(dst)), "l"(src));
}
__device__ __forceinline__ void cp_commit() {
    asm volatile("cp.async.commit_group;");
}
template <int N>
__device__ __forceinline__ void cp_wait() {
    asm volatile("cp.async.wait_group %0;" :: "n"(N));
}

// ---- P: his -> hisH (data cols only), W_att -> WTh; zero s_g ----
// Pad columns are never written: device globals are zero-initialized and
// no kernel ever writes non-zero there, so pads remain 0 across graph replays.
#define PRE_UNITS (PB*PK*PH*100)   // only the 100 real 4-col groups
__global__ void __launch_bounds__(256) preconv(
    const float* __restrict__ his, const float* __restrict__ W_att)
{
    const int u0 = blockIdx.x*256 + threadIdx.x;
    if (u0 < PB*PK*PH) s_g[u0] = 0.f;

    if (u0 < PK*PE*100) {
        const int ke = u0 / 100, d4 = u0 - ke*100;
        const int k = ke / PE, e = ke - k*PE;
        float w0 = W_att[((size_t)k*PD + d4*4    )*PE + e];
        float w1 = W_att[((size_t)k*PD + d4*4 + 1)*PE + e];
        float w2 = W_att[((size_t)k*PD + d4*4 + 2)*PE + e];
        float w3 = W_att[((size_t)k*PD + d4*4 + 3)*PE + e];
        *(ull*)(WTh + (size_t)ke*PDP + d4*4) = pack4h(w0, w1, w2, w3);
    }

    #pragma unroll
    for (int half = 0; half < 2; ++half) {
        const int u = u0 + half*(PRE_UNITS/2);
        if (u >= PRE_UNITS) break;
        const int bkh = u / 100, c4 = u - bkh*100;
        const int bk = bkh / PH, h = bkh - bk*PH;
        const int b = bk >> 2, k = bk & 3;
        float4 v = *(const float4*)(his + ((size_t)b*PH + h)*(PK*PD) + k*PD + c4*4);
        *(ull*)(hisH + (size_t)(bk*PH + h)*PDP + c4*4) = pack4h(v.x, v.y, v.z, v.w);
    }
}

// -----------------------------------------------------------------------------
// Kernel A1: m32-per-warp flat GEMM, KC=64, double-buffered cp.async, LDSM.
// B single-plane f16 (lo-plane dropped; error adds in quadrature -> ~3.3e-4).
// -----------------------------------------------------------------------------
__global__ void __launch_bounds__(256, 1) kernelA1(
    const float* __restrict__ b_att, const float* __restrict__ q_att)
{
    extern __shared__ __half smh[];

    const int tid  = threadIdx.x;
    const int warp = tid >> 5;
    const int lane = tid & 31;
    const int g    = lane >> 2;
    const int qq   = lane & 3;
    const int i8   = lane & 7;
    const int grp4 = lane >> 3;
    const int mrow0 = (warp >> 1) * 32;
    const int nbase = (warp & 1) * 104;

    const int mtile = blockIdx.x;
    const int k     = blockIdx.y;
    const int r0g   = mtile * 128;

    const __half* srcBH = WTh + (size_t)k*PE*PDP;

    auto load_tile = [&](int buf, int k0) {
        __half* aHi = smh + buf*BUF_HALVES;
        __half* bHi = aHi + A_PLANE;
        #pragma unroll
        for (int it = 0; it < 4; ++it) {
            int ua = tid + it*256;
            int row = ua >> 3, cc = ua & 7;
            int r = r0g + row;
            int b = r / 100, h = r - b*100;
            const __half* s = hisH + ((size_t)(b*4 + k)*PH + h)*PDP + k0 + cc*8;
            cp16(aHi + row*AS + cc*8, s);
        }
        // B hi only: 200 rows x 8 cc = 1600 units
        #pragma unroll
        for (int it = 0; it < 7; ++it) {
            int ub = tid + it*256;
            if (ub < 1600) {
                int row = ub >> 3, cc = ub & 7;
                const __half* s = srcBH + (size_t)row*PDP + k0 + cc*8;
                cp16(bHi + row*AS + cc*8, s);
            }
        }
    };

    const uint aoff  = (uint)(((mrow0 + (grp4 & 1)*8 + i8)*AS + (grp4 >> 1)*8) * 2);
    const uint boff  = (uint)(((nbase + (grp4 >> 1)*8 + i8)*AS + (grp4 & 1)*8) * 2);
    const uint boff2 = (uint)(((nbase + i8)*AS + ((lane >> 3) & 1)*8) * 2);

    float c[13][8];
    #pragma unroll
    for (int t = 0; t < 13; ++t)
        #pragma unroll
        for (int j = 0; j < 8; ++j) c[t][j] = 0.f;

    load_tile(0, 0);
    cp_commit();

    for (int ch = 0; ch < NCH; ++ch) {
        const int buf = ch & 1;
        if (ch < NCH - 1) {
            load_tile(buf ^ 1, (ch+1)*KC);
            cp_commit();
            cp_wait<1>();
        } else {
            cp_wait<0>();
        }
        __syncthreads();

        const uint aHiB = smem_u32(smh + buf*BUF_HALVES);
        const uint bHiB = aHiB + A_PLANE*2;

        #pragma unroll
        for (int ks = 0; ks < 4; ++ks) {
            const uint kk2 = (uint)(ks * 16 * 2);
            uint a0[4], a1[4];
            ldsm_x4(a0[0], a0[1], a0[2], a0[3], aHiB + aoff + kk2);
            ldsm_x4(a1[0], a1[1], a1[2], a1[3], aHiB + aoff + 16*AS*2 + kk2);
            #pragma unroll
            for (int t2 = 0; t2 < 6; ++t2) {
                const uint toff = (uint)(t2 * 16 * AS * 2);
                uint bh[4];
                ldsm_x4(bh[0], bh[1], bh[2], bh[3], bHiB + boff + toff + kk2);
                const int t = 2*t2;
                mma16816(c[t][0], c[t][1], c[t][2], c[t][3],
                         a0[0], a0[1], a0[2], a0[3], bh[0], bh[1]);
                mma16816(c[t][4], c[t][5], c[t][6], c[t][7],
                         a1[0], a1[1], a1[2], a1[3], bh[0], bh[1]);
                mma16816(c[t+1][0], c[t+1][1], c[t+1][2], c[t+1][3],
                         a0[0], a0[1], a0[2], a0[3], bh[2], bh[3]);
                mma16816(c[t+1][4], c[t+1][5], c[t+1][6], c[t+1][7],
                         a1[0], a1[1], a1[2], a1[3], bh[2], bh[3]);
            }
            {   // tile 12 (x2)
                const uint toff = (uint)(6 * 16 * AS * 2);
                uint bh0, bh1;
                ldsm_x2(bh0, bh1, bHiB + boff2 + toff + kk2);
                mma16816(c[12][0], c[12][1], c[12][2], c[12][3],
                         a0[0], a0[1], a0[2], a0[3], bh0, bh1);
                mma16816(c[12][4], c[12][5], c[12][6], c[12][7],
                         a1[0], a1[1], a1[2], a1[3], bh0, bh1);
            }
        }
        __syncthreads();
    }

    float pr[4] = {0.f, 0.f, 0.f, 0.f};
    #pragma unroll
    for (int t = 0; t < 13; ++t) {
        const int e0 = nbase + t*8 + qq*2;
        if (e0 < PE) {
            const float q0 = q_att[k*PE + e0],   bb0 = b_att[k*PE + e0];
            const float q1 = q_att[k*PE + e0+1], bb1 = b_att[k*PE + e0+1];
            pr[0] += q0 * tanh_fast(c[t][0] + bb0) + q1 * tanh_fast(c[t][1] + bb1);
            pr[1] += q0 * tanh_fast(c[t][2] + bb0) + q1 * tanh_fast(c[t][3] + bb1);
            pr[2] += q0 * tanh_fast(c[t][4] + bb0) + q1 * tanh_fast(c[t][5] + bb1);
            pr[3] += q0 * tanh_fast(c[t][6] + bb0) + q1 * tanh_fast(c[t][7] + bb1);
        }
    }
    #pragma unroll
    for (int i = 0; i < 4; ++i) {
        pr[i] += __shfl_xor_sync(0xffffffffu, pr[i], 1);
        pr[i] += __shfl_xor_sync(0xffffffffu, pr[i], 2);
    }
    if (qq == 0) {
        #pragma unroll
        for (int i = 0; i < 4; ++i) {
            int r = r0g + mrow0 + ((i & 1) ? 8 : 0) + ((i >> 1) ? 16 : 0) + g;
            int b = r / 100, h = r - b*100;
            atomicAdd(&s_g[(b*4 + k)*PH + h], pr[i]);
        }
    }
}

// ---- Kernel A2: unchanged (512 thr, split phases, writes out_u) ----
__global__ void __launch_bounds__(512) kernelA2(
    const float* __restrict__ W_lin, const float* __restrict__ b_lin,
    float* __restrict__ out_u)
{
    __shared__ float s_s[PH];
    __shared__ float u_s[PD];
    __shared__ float up2[PD];
    __shared__ float uwp[2][PE];
    __shared__ float red_s[2];

    const int bk = blockIdx.x;
    const int b = bk >> 2, k = bk & 3;
    const int tid = threadIdx.x;
    const int grp = tid >> 8;
    const int t   = tid & 255;
    const __half* hisB16 = hisH + (size_t)bk*PH*PDP;

    if (tid < PH) s_s[tid] = s_g[bk*PH + tid];
    __syncthreads();

    if (tid < 32) {
        float m = -1e30f;
        for (int h = tid; h < PH; h += 32) m = fmaxf(m, s_s[h]);
        #pragma unroll
        for (int off = 16; off; off >>= 1)
            m = fmaxf(m, __shfl_xor_sync(0xffffffffu, m, off));
        if (tid == 0) { red_s[0] = m; red_s[1] = 0.f; }
    }
    __syncthreads();
    const float mx = red_s[0];
    if (tid < PH) {
        float ex = __expf(s_s[tid] - mx);
        s_s[tid] = ex;
        atomicAdd(&red_s[1], ex);
    }
    __syncthreads();
    const float inv = 1.f / red_s[1];

    if (t < 200) {
        const int d2 = t;
        const int h0 = grp ? 52 : 0;
        const int h1 = grp ? 100 : 52;
        float a0 = 0.f, b0 = 0.f, a1 = 0.f, b1 = 0.f;
        float a2 = 0.f, b2 = 0.f, a3 = 0.f, b3 = 0.f;
        #pragma unroll 4
        for (int h = h0; h < h1; h += 4) {
            float2 v0 = __half22float2(*(const __half2*)(hisB16 + (size_t)h*PDP + 2*d2));
            float2 v1 = __half22float2(*(const __half2*)(hisB16 + (size_t)(h+1)*PDP + 2*d2));
            float2 v2 = __half22float2(*(const __half2*)(hisB16 + (size_t)(h+2)*PDP + 2*d2));
            float2 v3 = __half22float2(*(const __half2*)(hisB16 + (size_t)(h+3)*PDP + 2*d2));
            a0 += s_s[h]   * v0.x;  b0 += s_s[h]   * v0.y;
            a1 += s_s[h+1] * v1.x;  b1 += s_s[h+1] * v1.y;
            a2 += s_s[h+2] * v2.x;  b2 += s_s[h+2] * v2.y;
            a3 += s_s[h+3] * v3.x;  b3 += s_s[h+3] * v3.y;
        }
        float* dst = grp ? up2 : u_s;
        dst[2*d2]   = (a0 + a1) + (a2 + a3);
        dst[2*d2+1] = (b0 + b1) + (b2 + b3);
    }
    __syncthreads();

    if (tid < PD) {
        float uu = (u_s[tid] + up2[tid]) * inv;
        u_s[tid] = uu;
        u_g[bk*PD + tid] = uu;
    }
    __syncthreads();

    if (t < PE) {
        const int e = t;
        const int d0 = grp * 200;
        float a0 = 0.f, a1 = 0.f, a2 = 0.f, a3 = 0.f;
        float a4 = 0.f, a5 = 0.f, a6 = 0.f, a7 = 0.f;
        #pragma unroll 2
        for (int d = d0; d < d0 + 200; d += 8) {
            a0 += u_s[d]   * W_lin[(size_t)(d)*PE + e];
            a1 += u_s[d+1] * W_lin[(size_t)(d+1)*PE + e];
            a2 += u_s[d+2] * W_lin[(size_t)(d+2)*PE + e];
            a3 += u_s[d+3] * W_lin[(size_t)(d+3)*PE + e];
            a4 += u_s[d+4] * W_lin[(size_t)(d+4)*PE + e];
            a5 += u_s[d+5] * W_lin[(size_t)(d+5)*PE + e];
            a6 += u_s[d+6] * W_lin[(size_t)(d+6)*PE + e];
            a7 += u_s[d+7] * W_lin[(size_t)(d+7)*PE + e];
        }
        uwp[grp][e] = ((a0 + a1) + (a2 + a3)) + ((a4 + a5) + (a6 + a7));
    }
    __syncthreads();

    if (tid < PE)
        uW_g[bk*PE + tid] = b_lin[tid] + uwp[0][tid] + uwp[1][tid];

    for (int idx = tid; idx < 32*(PD/4); idx += 512) {
        int cc = idx / (PD/4), i4 = idx - cc*(PD/4);
        float4 v = *(const float4*)(u_s + i4*4);
        *(float4*)(out_u + ((size_t)(b*PC + cc)*PK + k)*PD + i4*4) = v;
    }
}

// ---- Kernel C1: unchanged ----
__global__ void __launch_bounds__(256) kernelC1(
    const float* __restrict__ cwt, const float* __restrict__ W_lin)
{
    extern __shared__ float sm[];
    float* W2 = sm;
    float* cw = W2 + PCW*PE;

    const int tid = threadIdx.x;
    const int tx = tid & 7;
    const int ty = tid >> 3;
    const int row0 = blockIdx.x * 64;

    for (int i = tid; i < PCW*PE; i += 256) W2[i] = W_lin[PD*PE + i];
    for (int i = tid; i < 64*PCW; i += 256) cw[i] = cwt[(size_t)row0*PCW + i];
    __syncthreads();

    ull acc2[2][12];
    float accS[2] = {0.f, 0.f};
    #pragma unroll
    for (int r = 0; r < 2; ++r)
        #pragma unroll
        for (int j = 0; j < 12; ++j) acc2[r][j] = 0ull;

    const float* c0p = cw + (ty*2)*PCW;
    const float* c1p = c0p + PCW;

    #pragma unroll 2
    for (int f = 0; f < PCW; ++f) {
        const float c0 = c0p[f], c1 = c1p[f];
        const ull cc0 = pack2(c0, c0), cc1 = pack2(c1, c1);
        const float* wrow = W2 + f*PE + tx*2;
        #pragma unroll
        for (int j = 0; j < 12; ++j) {
            ull w2v = *(const ull*)(wrow + j*16);
            fma2(acc2[0][j], cc0, w2v);
            fma2(acc2[1][j], cc1, w2v);
        }
        const float wl = W2[f*PE + 192 + tx];
        accS[0] += c0 * wl;
        accS[1] += c1 * wl;
    }

    #pragma unroll
    for (int rr = 0; rr < 2; ++rr) {
        const int gidx = row0 + ty*2 + rr;
        float* zrow = zC_g + (size_t)gidx*PE;
        #pragma unroll
        for (int j = 0; j < 12; ++j) {
            float z0, z1; unpack2(acc2[rr][j], z0, z1);
            zrow[tx*2 + j*16]     = z0;
            zrow[tx*2 + j*16 + 1] = z1;
        }
        zrow[192 + tx] = accS[rr];
    }
}

// ---- Kernel D: unchanged ----
__global__ void __launch_bounds__(128) kernelD(
    const float* __restrict__ cdd, const float* __restrict__ q_vec,
    float* __restrict__ out_scores)
{
    const int n = blockIdx.x;
    const int b = n >> 5;
    const int tid = threadIdx.x;
    const int k = tid >> 5;
    const int lane = tid & 31;
    __shared__ float dot_s[4];
    __shared__ float sk_s[4];

    {
        const float* z = zC_g + ((size_t)n*PK + k)*PE;
        const float* uWp = uW_g + ((b << 2) + k)*PE;
        float p = 0.f;
        #pragma unroll
        for (int e = lane; e < PE; e += 32)
            p += q_vec[e] * tanh_fast(z[e] + uWp[e]);
        #pragma unroll
        for (int off = 16; off; off >>= 1)
            p += __shfl_xor_sync(0xffffffffu, p, off);
        if (lane == 0) sk_s[k] = p;
    }
    {
        const float* up = u_g + (size_t)((b << 2) + k)*PD;
        const float* cp = cdd + ((size_t)n*PK + k)*PD;
        float a = 0.f;
        for (int d = lane; d < PD; d += 32) a += up[d] * cp[d];
        #pragma unroll
        for (int off = 16; off; off >>= 1)
            a += __shfl_xor_sync(0xffffffffu, a, off);
        if (lane == 0) dot_s[k] = a;
    }
    __syncthreads();

    if (tid == 0) {
        const float s0 = sk_s[0], s1 = sk_s[1], s2 = sk_s[2], s3 = sk_s[3];
        const float m = fmaxf(fmaxf(s0, s1), fmaxf(s2, s3));
        const float w0 = __expf(s0 - m), w1 = __expf(s1 - m);
        const float w2 = __expf(s2 - m), w3 = __expf(s3 - m);
        out_scores[n] = (w0*dot_s[0] + w1*dot_s[1] + w2*dot_s[2] + w3*dot_s[3])
                        / (w0 + w1 + w2 + w3);
    }
}

extern "C" void kernel_launch(void* const* d_in, const int* in_sizes, int n_in,
                              void* d_out, int out_size)
{
    const float* his   = (const float*)d_in[0];
    const float* cdd   = (const float*)d_in[1];
    const float* cwt   = (const float*)d_in[2];
    const float* W_att = (const float*)d_in[3];
    const float* b_att = (const float*)d_in[4];
    const float* q_att = (const float*)d_in[5];
    const float* W_lin = (const float*)d_in[6];
    const float* b_lin = (const float*)d_in[7];
    const float* q_vec = (const float*)d_in[8];
    float* out = (float*)d_out;
    (void)in_sizes; (void)n_in; (void)out_size;

    static cudaStream_t s2 = nullptr;
    static cudaEvent_t evFork = nullptr, evJoin = nullptr;
    if (s2 == nullptr) {
        cudaStreamCreateWithFlags(&s2, cudaStreamNonBlocking);
        cudaEventCreateWithFlags(&evFork, cudaEventDisableTiming);
        cudaEventCreateWithFlags(&evJoin, cudaEventDisableTiming);
    }

    const int smemC = (PCW*PE + 64*PCW) * (int)sizeof(float);
    cudaFuncSetAttribute(kernelC1, cudaFuncAttributeMaxDynamicSharedMemorySize, smemC);
    cudaFuncSetAttribute(kernelA1, cudaFuncAttributeMaxDynamicSharedMemorySize, SMEMA_BYTES);

    cudaEventRecord(evFork, 0);
    cudaStreamWaitEvent(s2, evFork, 0);
    kernelC1<<<(PN*PK)/64, 256, smemC, s2>>>(cwt, W_lin);

    preconv<<<(PRE_UNITS/2 + 255)/256, 256>>>(his, W_att);
    kernelA1<<<dim3(100, 4), 256, SMEMA_BYTES>>>(b_att, q_att);
    kernelA2<<<PB*PK, 512>>>(W_lin, b_lin, out + PN);

    cudaEventRecord(evJoin, s2);
    cudaStreamWaitEvent(0, evJoin, 0);
    kernelD<<<PN, 128>>>(cdd, q_vec, out);
}

// round 17
// speedup vs baseline: 1.2349x; 1.0324x over previous
#include <cuda_runtime.h>
#include <cuda_fp16.h>
#include <math.h>

#define PB  128
#define PH  100
#define PC  32
#define PK  4
#define PD  400
#define PDP 448
#define PE  200
#define PCW 100
#define PN  (PB*PC)

#define KC   64
#define NCH  7
#define AS   72                      // smem row stride (halves) = 144B
#define A_PLANE (128*AS)             // 9216 halves
#define B_PLANE (208*AS)             // 14976 halves
#define BUF_HALVES (A_PLANE + B_PLANE)         // 24192 halves (B hi only)
#define SMEMA_BYTES (2*BUF_HALVES*2)           // 96768 B

typedef unsigned long long ull;
typedef unsigned int uint;

__device__ __align__(16) float u_g[PB*PK*PD];
__device__ __align__(16) float uW_g[PB*PK*PE];
__device__ __align__(16) float s_g[PB*PK*PH];
__device__ __align__(16) float zC_g[(size_t)PN*PK*PE];

__device__ __align__(16) __half hisH[PB*PK*PH*PDP];   // pads stay 0 (zero-init)
__device__ __align__(16) __half WTh[PK*PE*PDP];       // pads stay 0 (zero-init)

// ---- helpers ----
__device__ __forceinline__ ull pack2(float a, float b) {
    ull r; asm("mov.b64 %0, {%1, %2};" : "=l"(r) : "f"(a), "f"(b)); return r;
}
__device__ __forceinline__ void unpack2(ull v, float& a, float& b) {
    asm("mov.b64 {%0, %1}, %2;" : "=f"(a), "=f"(b) : "l"(v));
}
__device__ __forceinline__ void fma2(ull& d, ull a, ull b) {
    asm("fma.rn.f32x2 %0, %1, %2, %0;" : "+l"(d) : "l"(a), "l"(b));
}
__device__ __forceinline__ float tanh_fast(float x) {
    return __fdividef(2.f, 1.f + __expf(-2.f * x)) - 1.f;
}
__device__ __forceinline__ void mma16816(
    float& c0, float& c1, float& c2, float& c3,
    uint a0, uint a1, uint a2, uint a3, uint b0, uint b1)
{
    asm volatile(
        "mma.sync.aligned.m16n8k16.row.col.f32.f16.f16.f32 "
        "{%0,%1,%2,%3}, {%4,%5,%6,%7}, {%8,%9}, {%0,%1,%2,%3};"
        : "+f"(c0), "+f"(c1), "+f"(c2), "+f"(c3)
        : "r"(a0), "r"(a1), "r"(a2), "r"(a3), "r"(b0), "r"(b1));
}
__device__ __forceinline__ void ldsm_x4(uint& r0, uint& r1, uint& r2, uint& r3, uint addr) {
    asm volatile("ldmatrix.sync.aligned.m8n8.x4.shared.b16 {%0,%1,%2,%3}, [%4];"
                 : "=r"(r0), "=r"(r1), "=r"(r2), "=r"(r3) : "r"(addr));
}
__device__ __forceinline__ void ldsm_x2(uint& r0, uint& r1, uint addr) {
    asm volatile("ldmatrix.sync.aligned.m8n8.x2.shared.b16 {%0,%1}, [%2];"
                 : "=r"(r0), "=r"(r1) : "r"(addr));
}
__device__ __forceinline__ ull pack4h(float x0, float x1, float x2, float x3) {
    __half2 h01 = __halves2half2(__float2half_rn(x0), __float2half_rn(x1));
    __half2 h23 = __halves2half2(__float2half_rn(x2), __float2half_rn(x3));
    uint u0 = *(uint*)&h01, u1 = *(uint*)&h23;
    return (ull)u0 | ((ull)u1 << 32);
}
__device__ __forceinline__ unsigned smem_u32(const void* p) {
    return (unsigned)__cvta_generic_to_shared(p);
}
__device__ __forceinline__ void cp16(__half* dst, const __half* src) {
    asm volatile("cp.async.cg.shared.global [%0], [%1], 16;"
                 :: "r"(smem_u32(dst)), "l"(src));
}
__device__ __forceinline__ void cp_commit() {
    asm volatile("cp.async.commit_group;");
}
template <int N>
__device__ __forceinline__ void cp_wait() {
    asm volatile("cp.async.wait_group %0;" :: "n"(N));
}

// ---- P: his -> hisH (data cols only), W_att -> WTh; zero s_g ----
#define PRE_UNITS (PB*PK*PH*100)
__global__ void __launch_bounds__(256) preconv(
    const float* __restrict__ his, const float* __restrict__ W_att)
{
    const int u0 = blockIdx.x*256 + threadIdx.x;
    if (u0 < PB*PK*PH) s_g[u0] = 0.f;

    if (u0 < PK*PE*100) {
        const int ke = u0 / 100, d4 = u0 - ke*100;
        const int k = ke / PE, e = ke - k*PE;
        float w0 = W_att[((size_t)k*PD + d4*4    )*PE + e];
        float w1 = W_att[((size_t)k*PD + d4*4 + 1)*PE + e];
        float w2 = W_att[((size_t)k*PD + d4*4 + 2)*PE + e];
        float w3 = W_att[((size_t)k*PD + d4*4 + 3)*PE + e];
        *(ull*)(WTh + (size_t)ke*PDP + d4*4) = pack4h(w0, w1, w2, w3);
    }

    #pragma unroll
    for (int half = 0; half < 2; ++half) {
        const int u = u0 + half*(PRE_UNITS/2);
        if (u >= PRE_UNITS) break;
        const int bkh = u / 100, c4 = u - bkh*100;
        const int bk = bkh / PH, h = bkh - bk*PH;
        const int b = bk >> 2, k = bk & 3;
        float4 v = *(const float4*)(his + ((size_t)b*PH + h)*(PK*PD) + k*PD + c4*4);
        *(ull*)(hisH + (size_t)(bk*PH + h)*PDP + c4*4) = pack4h(v.x, v.y, v.z, v.w);
    }
}

// -----------------------------------------------------------------------------
// Kernel A1: m32-per-warp flat GEMM, KC=64, double-buffered cp.async, LDSM,
// B single-plane. NOW 2 blocks/SM (reg cap 128) for cross-block overlap.
// -----------------------------------------------------------------------------
__global__ void __launch_bounds__(256, 2) kernelA1(
    const float* __restrict__ b_att, const float* __restrict__ q_att)
{
    extern __shared__ __half smh[];

    const int tid  = threadIdx.x;
    const int warp = tid >> 5;
    const int lane = tid & 31;
    const int g    = lane >> 2;
    const int qq   = lane & 3;
    const int i8   = lane & 7;
    const int grp4 = lane >> 3;
    const int mrow0 = (warp >> 1) * 32;
    const int nbase = (warp & 1) * 104;

    const int mtile = blockIdx.x;
    const int k     = blockIdx.y;
    const int r0g   = mtile * 128;

    const __half* srcBH = WTh + (size_t)k*PE*PDP;

    auto load_tile = [&](int buf, int k0) {
        __half* aHi = smh + buf*BUF_HALVES;
        __half* bHi = aHi + A_PLANE;
        #pragma unroll
        for (int it = 0; it < 4; ++it) {
            int ua = tid + it*256;
            int row = ua >> 3, cc = ua & 7;
            int r = r0g + row;
            int b = r / 100, h = r - b*100;
            const __half* s = hisH + ((size_t)(b*4 + k)*PH + h)*PDP + k0 + cc*8;
            cp16(aHi + row*AS + cc*8, s);
        }
        #pragma unroll
        for (int it = 0; it < 7; ++it) {
            int ub = tid + it*256;
            if (ub < 1600) {
                int row = ub >> 3, cc = ub & 7;
                const __half* s = srcBH + (size_t)row*PDP + k0 + cc*8;
                cp16(bHi + row*AS + cc*8, s);
            }
        }
    };

    const uint aoff  = (uint)(((mrow0 + (grp4 & 1)*8 + i8)*AS + (grp4 >> 1)*8) * 2);
    const uint boff  = (uint)(((nbase + (grp4 >> 1)*8 + i8)*AS + (grp4 & 1)*8) * 2);
    const uint boff2 = (uint)(((nbase + i8)*AS + ((lane >> 3) & 1)*8) * 2);

    float c[13][8];
    #pragma unroll
    for (int t = 0; t < 13; ++t)
        #pragma unroll
        for (int j = 0; j < 8; ++j) c[t][j] = 0.f;

    load_tile(0, 0);
    cp_commit();

    for (int ch = 0; ch < NCH; ++ch) {
        const int buf = ch & 1;
        if (ch < NCH - 1) {
            load_tile(buf ^ 1, (ch+1)*KC);
            cp_commit();
            cp_wait<1>();
        } else {
            cp_wait<0>();
        }
        __syncthreads();

        const uint aHiB = smem_u32(smh + buf*BUF_HALVES);
        const uint bHiB = aHiB + A_PLANE*2;

        #pragma unroll
        for (int ks = 0; ks < 4; ++ks) {
            const uint kk2 = (uint)(ks * 16 * 2);
            uint a0[4], a1[4];
            ldsm_x4(a0[0], a0[1], a0[2], a0[3], aHiB + aoff + kk2);
            ldsm_x4(a1[0], a1[1], a1[2], a1[3], aHiB + aoff + 16*AS*2 + kk2);
            #pragma unroll
            for (int t2 = 0; t2 < 6; ++t2) {
                const uint toff = (uint)(t2 * 16 * AS * 2);
                uint bh[4];
                ldsm_x4(bh[0], bh[1], bh[2], bh[3], bHiB + boff + toff + kk2);
                const int t = 2*t2;
                mma16816(c[t][0], c[t][1], c[t][2], c[t][3],
                         a0[0], a0[1], a0[2], a0[3], bh[0], bh[1]);
                mma16816(c[t][4], c[t][5], c[t][6], c[t][7],
                         a1[0], a1[1], a1[2], a1[3], bh[0], bh[1]);
                mma16816(c[t+1][0], c[t+1][1], c[t+1][2], c[t+1][3],
                         a0[0], a0[1], a0[2], a0[3], bh[2], bh[3]);
                mma16816(c[t+1][4], c[t+1][5], c[t+1][6], c[t+1][7],
                         a1[0], a1[1], a1[2], a1[3], bh[2], bh[3]);
            }
            {   // tile 12 (x2)
                const uint toff = (uint)(6 * 16 * AS * 2);
                uint bh0, bh1;
                ldsm_x2(bh0, bh1, bHiB + boff2 + toff + kk2);
                mma16816(c[12][0], c[12][1], c[12][2], c[12][3],
                         a0[0], a0[1], a0[2], a0[3], bh0, bh1);
                mma16816(c[12][4], c[12][5], c[12][6], c[12][7],
                         a1[0], a1[1], a1[2], a1[3], bh0, bh1);
            }
        }
        __syncthreads();
    }

    float pr[4] = {0.f, 0.f, 0.f, 0.f};
    #pragma unroll
    for (int t = 0; t < 13; ++t) {
        const int e0 = nbase + t*8 + qq*2;
        if (e0 < PE) {
            const float q0 = q_att[k*PE + e0],   bb0 = b_att[k*PE + e0];
            const float q1 = q_att[k*PE + e0+1], bb1 = b_att[k*PE + e0+1];
            pr[0] += q0 * tanh_fast(c[t][0] + bb0) + q1 * tanh_fast(c[t][1] + bb1);
            pr[1] += q0 * tanh_fast(c[t][2] + bb0) + q1 * tanh_fast(c[t][3] + bb1);
            pr[2] += q0 * tanh_fast(c[t][4] + bb0) + q1 * tanh_fast(c[t][5] + bb1);
            pr[3] += q0 * tanh_fast(c[t][6] + bb0) + q1 * tanh_fast(c[t][7] + bb1);
        }
    }
    #pragma unroll
    for (int i = 0; i < 4; ++i) {
        pr[i] += __shfl_xor_sync(0xffffffffu, pr[i], 1);
        pr[i] += __shfl_xor_sync(0xffffffffu, pr[i], 2);
    }
    if (qq == 0) {
        #pragma unroll
        for (int i = 0; i < 4; ++i) {
            int r = r0g + mrow0 + ((i & 1) ? 8 : 0) + ((i >> 1) ? 16 : 0) + g;
            int b = r / 100, h = r - b*100;
            atomicAdd(&s_g[(b*4 + k)*PH + h], pr[i]);
        }
    }
}

// ---- Kernel A2: unchanged ----
__global__ void __launch_bounds__(512) kernelA2(
    const float* __restrict__ W_lin, const float* __restrict__ b_lin,
    float* __restrict__ out_u)
{
    __shared__ float s_s[PH];
    __shared__ float u_s[PD];
    __shared__ float up2[PD];
    __shared__ float uwp[2][PE];
    __shared__ float red_s[2];

    const int bk = blockIdx.x;
    const int b = bk >> 2, k = bk & 3;
    const int tid = threadIdx.x;
    const int grp = tid >> 8;
    const int t   = tid & 255;
    const __half* hisB16 = hisH + (size_t)bk*PH*PDP;

    if (tid < PH) s_s[tid] = s_g[bk*PH + tid];
    __syncthreads();

    if (tid < 32) {
        float m = -1e30f;
        for (int h = tid; h < PH; h += 32) m = fmaxf(m, s_s[h]);
        #pragma unroll
        for (int off = 16; off; off >>= 1)
            m = fmaxf(m, __shfl_xor_sync(0xffffffffu, m, off));
        if (tid == 0) { red_s[0] = m; red_s[1] = 0.f; }
    }
    __syncthreads();
    const float mx = red_s[0];
    if (tid < PH) {
        float ex = __expf(s_s[tid] - mx);
        s_s[tid] = ex;
        atomicAdd(&red_s[1], ex);
    }
    __syncthreads();
    const float inv = 1.f / red_s[1];

    if (t < 200) {
        const int d2 = t;
        const int h0 = grp ? 52 : 0;
        const int h1 = grp ? 100 : 52;
        float a0 = 0.f, b0 = 0.f, a1 = 0.f, b1 = 0.f;
        float a2 = 0.f, b2 = 0.f, a3 = 0.f, b3 = 0.f;
        #pragma unroll 4
        for (int h = h0; h < h1; h += 4) {
            float2 v0 = __half22float2(*(const __half2*)(hisB16 + (size_t)h*PDP + 2*d2));
            float2 v1 = __half22float2(*(const __half2*)(hisB16 + (size_t)(h+1)*PDP + 2*d2));
            float2 v2 = __half22float2(*(const __half2*)(hisB16 + (size_t)(h+2)*PDP + 2*d2));
            float2 v3 = __half22float2(*(const __half2*)(hisB16 + (size_t)(h+3)*PDP + 2*d2));
            a0 += s_s[h]   * v0.x;  b0 += s_s[h]   * v0.y;
            a1 += s_s[h+1] * v1.x;  b1 += s_s[h+1] * v1.y;
            a2 += s_s[h+2] * v2.x;  b2 += s_s[h+2] * v2.y;
            a3 += s_s[h+3] * v3.x;  b3 += s_s[h+3] * v3.y;
        }
        float* dst = grp ? up2 : u_s;
        dst[2*d2]   = (a0 + a1) + (a2 + a3);
        dst[2*d2+1] = (b0 + b1) + (b2 + b3);
    }
    __syncthreads();

    if (tid < PD) {
        float uu = (u_s[tid] + up2[tid]) * inv;
        u_s[tid] = uu;
        u_g[bk*PD + tid] = uu;
    }
    __syncthreads();

    if (t < PE) {
        const int e = t;
        const int d0 = grp * 200;
        float a0 = 0.f, a1 = 0.f, a2 = 0.f, a3 = 0.f;
        float a4 = 0.f, a5 = 0.f, a6 = 0.f, a7 = 0.f;
        #pragma unroll 2
        for (int d = d0; d < d0 + 200; d += 8) {
            a0 += u_s[d]   * W_lin[(size_t)(d)*PE + e];
            a1 += u_s[d+1] * W_lin[(size_t)(d+1)*PE + e];
            a2 += u_s[d+2] * W_lin[(size_t)(d+2)*PE + e];
            a3 += u_s[d+3] * W_lin[(size_t)(d+3)*PE + e];
            a4 += u_s[d+4] * W_lin[(size_t)(d+4)*PE + e];
            a5 += u_s[d+5] * W_lin[(size_t)(d+5)*PE + e];
            a6 += u_s[d+6] * W_lin[(size_t)(d+6)*PE + e];
            a7 += u_s[d+7] * W_lin[(size_t)(d+7)*PE + e];
        }
        uwp[grp][e] = ((a0 + a1) + (a2 + a3)) + ((a4 + a5) + (a6 + a7));
    }
    __syncthreads();

    if (tid < PE)
        uW_g[bk*PE + tid] = b_lin[tid] + uwp[0][tid] + uwp[1][tid];

    for (int idx = tid; idx < 32*(PD/4); idx += 512) {
        int cc = idx / (PD/4), i4 = idx - cc*(PD/4);
        float4 v = *(const float4*)(u_s + i4*4);
        *(float4*)(out_u + ((size_t)(b*PC + cc)*PK + k)*PD + i4*4) = v;
    }
}

// ---- Kernel C1: unchanged ----
__global__ void __launch_bounds__(256) kernelC1(
    const float* __restrict__ cwt, const float* __restrict__ W_lin)
{
    extern __shared__ float sm[];
    float* W2 = sm;
    float* cw = W2 + PCW*PE;

    const int tid = threadIdx.x;
    const int tx = tid & 7;
    const int ty = tid >> 3;
    const int row0 = blockIdx.x * 64;

    for (int i = tid; i < PCW*PE; i += 256) W2[i] = W_lin[PD*PE + i];
    for (int i = tid; i < 64*PCW; i += 256) cw[i] = cwt[(size_t)row0*PCW + i];
    __syncthreads();

    ull acc2[2][12];
    float accS[2] = {0.f, 0.f};
    #pragma unroll
    for (int r = 0; r < 2; ++r)
        #pragma unroll
        for (int j = 0; j < 12; ++j) acc2[r][j] = 0ull;

    const float* c0p = cw + (ty*2)*PCW;
    const float* c1p = c0p + PCW;

    #pragma unroll 2
    for (int f = 0; f < PCW; ++f) {
        const float c0 = c0p[f], c1 = c1p[f];
        const ull cc0 = pack2(c0, c0), cc1 = pack2(c1, c1);
        const float* wrow = W2 + f*PE + tx*2;
        #pragma unroll
        for (int j = 0; j < 12; ++j) {
            ull w2v = *(const ull*)(wrow + j*16);
            fma2(acc2[0][j], cc0, w2v);
            fma2(acc2[1][j], cc1, w2v);
        }
        const float wl = W2[f*PE + 192 + tx];
        accS[0] += c0 * wl;
        accS[1] += c1 * wl;
    }

    #pragma unroll
    for (int rr = 0; rr < 2; ++rr) {
        const int gidx = row0 + ty*2 + rr;
        float* zrow = zC_g + (size_t)gidx*PE;
        #pragma unroll
        for (int j = 0; j < 12; ++j) {
            float z0, z1; unpack2(acc2[rr][j], z0, z1);
            zrow[tx*2 + j*16]     = z0;
            zrow[tx*2 + j*16 + 1] = z1;
        }
        zrow[192 + tx] = accS[rr];
    }
}

// ---- Kernel D: unchanged ----
__global__ void __launch_bounds__(128) kernelD(
    const float* __restrict__ cdd, const float* __restrict__ q_vec,
    float* __restrict__ out_scores)
{
    const int n = blockIdx.x;
    const int b = n >> 5;
    const int tid = threadIdx.x;
    const int k = tid >> 5;
    const int lane = tid & 31;
    __shared__ float dot_s[4];
    __shared__ float sk_s[4];

    {
        const float* z = zC_g + ((size_t)n*PK + k)*PE;
        const float* uWp = uW_g + ((b << 2) + k)*PE;
        float p = 0.f;
        #pragma unroll
        for (int e = lane; e < PE; e += 32)
            p += q_vec[e] * tanh_fast(z[e] + uWp[e]);
        #pragma unroll
        for (int off = 16; off; off >>= 1)
            p += __shfl_xor_sync(0xffffffffu, p, off);
        if (lane == 0) sk_s[k] = p;
    }
    {
        const float* up = u_g + (size_t)((b << 2) + k)*PD;
        const float* cp = cdd + ((size_t)n*PK + k)*PD;
        float a = 0.f;
        for (int d = lane; d < PD; d += 32) a += up[d] * cp[d];
        #pragma unroll
        for (int off = 16; off; off >>= 1)
            a += __shfl_xor_sync(0xffffffffu, a, off);
        if (lane == 0) dot_s[k] = a;
    }
    __syncthreads();

    if (tid == 0) {
        const float s0 = sk_s[0], s1 = sk_s[1], s2 = sk_s[2], s3 = sk_s[3];
        const float m = fmaxf(fmaxf(s0, s1), fmaxf(s2, s3));
        const float w0 = __expf(s0 - m), w1 = __expf(s1 - m);
        const float w2 = __expf(s2 - m), w3 = __expf(s3 - m);
        out_scores[n] = (w0*dot_s[0] + w1*dot_s[1] + w2*dot_s[2] + w3*dot_s[3])
                        / (w0 + w1 + w2 + w3);
    }
}

extern "C" void kernel_launch(void* const* d_in, const int* in_sizes, int n_in,
                              void* d_out, int out_size)
{
    const float* his   = (const float*)d_in[0];
    const float* cdd   = (const float*)d_in[1];
    const float* cwt   = (const float*)d_in[2];
    const float* W_att = (const float*)d_in[3];
    const float* b_att = (const float*)d_in[4];
    const float* q_att = (const float*)d_in[5];
    const float* W_lin = (const float*)d_in[6];
    const float* b_lin = (const float*)d_in[7];
    const float* q_vec = (const float*)d_in[8];
    float* out = (float*)d_out;
    (void)in_sizes; (void)n_in; (void)out_size;

    static cudaStream_t s2 = nullptr;
    static cudaEvent_t evFork = nullptr, evJoin = nullptr;
    if (s2 == nullptr) {
        cudaStreamCreateWithFlags(&s2, cudaStreamNonBlocking);
        cudaEventCreateWithFlags(&evFork, cudaEventDisableTiming);
        cudaEventCreateWithFlags(&evJoin, cudaEventDisableTiming);
    }

    const int smemC = (PCW*PE + 64*PCW) * (int)sizeof(float);
    cudaFuncSetAttribute(kernelC1, cudaFuncAttributeMaxDynamicSharedMemorySize, smemC);
    cudaFuncSetAttribute(kernelA1, cudaFuncAttributeMaxDynamicSharedMemorySize, SMEMA_BYTES);

    cudaEventRecord(evFork, 0);
    cudaStreamWaitEvent(s2, evFork, 0);
    kernelC1<<<(PN*PK)/64, 256, smemC, s2>>>(cwt, W_lin);

    preconv<<<(PRE_UNITS/2 + 255)/256, 256>>>(his, W_att);
    kernelA1<<<dim3(100, 4), 256, SMEMA_BYTES>>>(b_att, q_att);
    kernelA2<<<PB*PK, 512>>>(W_lin, b_lin, out + PN);

    cudaEventRecord(evJoin, s2);
    cudaStreamWaitEvent(0, evJoin, 0);
    kernelD<<<PN, 128>>>(cdd, q_vec, out);
}